// round 4
// baseline (speedup 1.0000x reference)
#include <cuda_runtime.h>

#define NN 100000
#define NE 1200000
#define DD 64
#define ADJ_STRIDE 128
#define OVF_CAP 8192

// Scratch (device globals — no allocation allowed)
__device__ float g_H[NN * DD];            // gather source (normalized features)
__device__ float g_AGG[NN * DD];          // aggregation result
__device__ int   g_degout[NN];
__device__ int   g_cnt[NN];               // in-degree == adjacency fill count
__device__ float g_nout[NN];
__device__ float g_nin[NN];
__device__ int   g_adj[NN * ADJ_STRIDE];  // padded in-adjacency: src ids per dst
__device__ int   g_ovf[OVF_CAP];          // overflow edge indices (should stay empty)
__device__ int   g_ovf_cnt;

// ---------------------------------------------------------------------------
__global__ void k_zero() {
    int i = blockIdx.x * blockDim.x + threadIdx.x;
    if (i < NN) { g_degout[i] = 0; g_cnt[i] = 0; }
    if (i == 0) g_ovf_cnt = 0;
}

// Count out-degree; bucket edges by dst into padded adjacency.
__global__ void k_build(const int* __restrict__ src, const int* __restrict__ dst) {
    int e = blockIdx.x * blockDim.x + threadIdx.x;
    if (e >= NE) return;
    int s = src[e], d = dst[e];
    atomicAdd(&g_degout[s], 1);
    int slot = atomicAdd(&g_cnt[d], 1);
    if (slot < ADJ_STRIDE) {
        g_adj[d * ADJ_STRIDE + slot] = s;
    } else {
        int o = atomicAdd(&g_ovf_cnt, 1);
        if (o < OVF_CAP) g_ovf[o] = e;
    }
}

__global__ void k_norm() {
    int i = blockIdx.x * blockDim.x + threadIdx.x;
    if (i < NN) {
        g_nout[i] = rsqrtf(fmaxf((float)g_degout[i], 1.0f));
        g_nin[i]  = rsqrtf(fmaxf((float)g_cnt[i],    1.0f));
    }
}

// H = feats * norm_out[row]
__global__ void k_scale(const float4* __restrict__ feats) {
    int t = blockIdx.x * blockDim.x + threadIdx.x;
    if (t < NN * (DD / 4)) {
        int row = t >> 4;
        float s = g_nout[row];
        float4 v = feats[t];
        v.x *= s; v.y *= s; v.z *= s; v.w *= s;
        reinterpret_cast<float4*>(g_H)[t] = v;
    }
}

// Pure-gather SpMM: 16 threads per node, thread j owns float4 lane j.
// AGG[n] = sum over in-edges (s -> n) of H[s].   (Overwrites AGG.)
__global__ void __launch_bounds__(256) k_agg() {
    int t = blockIdx.x * blockDim.x + threadIdx.x;
    if (t >= NN * 16) return;
    int n = t >> 4;
    int j = t & 15;
    int cnt = g_cnt[n];
    if (cnt > ADJ_STRIDE) cnt = ADJ_STRIDE;
    const int* lst = &g_adj[n * ADJ_STRIDE];
    const float4* H4 = reinterpret_cast<const float4*>(g_H);
    float4 acc = make_float4(0.f, 0.f, 0.f, 0.f);
    int k = 0;
    for (; k + 4 <= cnt; k += 4) {
        int s0 = __ldg(&lst[k + 0]);
        int s1 = __ldg(&lst[k + 1]);
        int s2 = __ldg(&lst[k + 2]);
        int s3 = __ldg(&lst[k + 3]);
        float4 v0 = H4[s0 * 16 + j];
        float4 v1 = H4[s1 * 16 + j];
        float4 v2 = H4[s2 * 16 + j];
        float4 v3 = H4[s3 * 16 + j];
        acc.x += v0.x + v1.x + v2.x + v3.x;
        acc.y += v0.y + v1.y + v2.y + v3.y;
        acc.z += v0.z + v1.z + v2.z + v3.z;
        acc.w += v0.w + v1.w + v2.w + v3.w;
    }
    for (; k < cnt; k++) {
        int s = __ldg(&lst[k]);
        float4 v = H4[s * 16 + j];
        acc.x += v.x; acc.y += v.y; acc.z += v.z; acc.w += v.w;
    }
    reinterpret_cast<float4*>(g_AGG)[t] = acc;
}

// Overflow edges (expected zero): scalar atomic add H[s] into AGG[d].
__global__ void k_ovf(const int* __restrict__ src, const int* __restrict__ dst) {
    int cnt = g_ovf_cnt;
    if (cnt > OVF_CAP) cnt = OVF_CAP;
    for (int idx = threadIdx.x; idx < cnt * 16; idx += blockDim.x) {
        int e = g_ovf[idx >> 4];
        int j = idx & 15;
        int s = src[e], d = dst[e];
        const float* h = &g_H[s * DD + j * 4];
        float* a = &g_AGG[d * DD + j * 4];
        atomicAdd(&a[0], h[0]);
        atomicAdd(&a[1], h[1]);
        atomicAdd(&a[2], h[2]);
        atomicAdd(&a[3], h[3]);
    }
}

// Fused epilogue GEMM:  dst[row] = epi( (AGG[row]*norm_in[row]) @ W + b )
// RELU_NORM: epi = relu(.)*norm_out[row], dst = g_H (device symbol resolved
// IN DEVICE CODE — passing g_H from host code yields the host shadow address,
// which on GB300/ATS silently lands in host memory; that was the R1-R3 bug).
// else: epi = identity, dst = out_param (harness d_out).
template <bool RELU_NORM>
__global__ void __launch_bounds__(256)
k_gemm(const float* __restrict__ W, const float* __restrict__ b,
       float* __restrict__ out_param) {
    __shared__ float  Wt[64 * 68];       // Wt[c*68 + k] = W[k*64 + c]
    __shared__ float  bs[64];
    __shared__ float4 rows[16 * 16];     // 16 rows x 16 float4

    float* out = RELU_NORM ? g_H : out_param;   // device-side symbol resolution

    int t = threadIdx.x;
    for (int i = t; i < 4096; i += 256) {
        int k = i >> 6, c = i & 63;
        Wt[c * 68 + k] = W[i];
    }
    if (t < 64) bs[t] = b[t];
    __syncthreads();

    const int c  = t & 63;
    const int rg = t >> 6;                   // 0..3
    const float4* wrow = reinterpret_cast<const float4*>(&Wt[c * 68]);

    for (int tile = blockIdx.x; tile < NN / 16; tile += gridDim.x) {
        {
            float4 v = reinterpret_cast<const float4*>(g_AGG)[tile * 256 + t];
            int row = tile * 16 + (t >> 4);
            float s = g_nin[row];
            v.x *= s; v.y *= s; v.z *= s; v.w *= s;
            rows[t] = v;
        }
        __syncthreads();

        float acc0 = 0.f, acc1 = 0.f, acc2 = 0.f, acc3 = 0.f;
        const float4* r0 = &rows[(rg * 4 + 0) * 16];
        const float4* r1 = &rows[(rg * 4 + 1) * 16];
        const float4* r2 = &rows[(rg * 4 + 2) * 16];
        const float4* r3 = &rows[(rg * 4 + 3) * 16];
        #pragma unroll
        for (int k4 = 0; k4 < 16; k4++) {
            float4 w = wrow[k4];
            float4 a;
            a = r0[k4]; acc0 += a.x*w.x + a.y*w.y + a.z*w.z + a.w*w.w;
            a = r1[k4]; acc1 += a.x*w.x + a.y*w.y + a.z*w.z + a.w*w.w;
            a = r2[k4]; acc2 += a.x*w.x + a.y*w.y + a.z*w.z + a.w*w.w;
            a = r3[k4]; acc3 += a.x*w.x + a.y*w.y + a.z*w.z + a.w*w.w;
        }

        float accs[4] = {acc0, acc1, acc2, acc3};
        #pragma unroll
        for (int rr = 0; rr < 4; rr++) {
            int row = tile * 16 + rg * 4 + rr;
            float val = accs[rr] + bs[c];
            if (RELU_NORM) val = fmaxf(val, 0.f) * g_nout[row];
            out[row * DD + c] = val;
        }
        __syncthreads();
    }
}

// ---------------------------------------------------------------------------
extern "C" void kernel_launch(void* const* d_in, const int* in_sizes, int n_in,
                              void* d_out, int out_size) {
    // Size-based input dispatch (robust to metadata ordering).
    const float* feats = 0;
    const int*   edgeA = 0;   // first 1.2M-int tensor seen
    const int*   edgeB = 0;   // second
    const float* Wv[2] = {0, 0};
    const float* bv[2] = {0, 0};
    int wi = 0, bi = 0;
    for (int i = 0; i < n_in; i++) {
        int sz = in_sizes[i];
        if (sz == NN * DD) {
            feats = (const float*)d_in[i];
        } else if (sz == NE) {
            if (!edgeA) edgeA = (const int*)d_in[i];
            else        edgeB = (const int*)d_in[i];
        } else if (sz == DD * DD) {
            if (wi < 2) Wv[wi++] = (const float*)d_in[i];
        } else if (sz == DD) {
            if (bi < 2) bv[bi++] = (const float*)d_in[i];
        }
    }
    // Insertion (metadata.txt) order: src precedes dst.
    const int* src = edgeA;
    const int* dst = edgeB;
    const float* W1 = Wv[0]; const float* b1 = bv[0];
    const float* W2 = Wv[1]; const float* b2 = bv[1];
    float* out = (float*)d_out;

    const int T = 256;
    const int g_nodes = (NN + T - 1) / T;
    const int g_edges = (NE + T - 1) / T;
    const int g_vec   = (NN * 16 + T - 1) / T;   // 6250
    const int g_gemm  = 1184;

    // Graph structure (shared by both layers)
    k_zero<<<g_nodes, T>>>();
    k_build<<<g_edges, T>>>(src, dst);
    k_norm<<<g_nodes, T>>>();

    // Layer 1
    k_scale<<<g_vec, T>>>((const float4*)feats);   // H = feats * nout
    k_agg<<<g_vec, T>>>();                          // AGG = gather-sum H[adj]
    k_ovf<<<1, 256>>>(src, dst);
    k_gemm<true><<<g_gemm, T>>>(W1, b1, 0);         // H = relu(AGG*nin@W1+b1)*nout
    // Layer 2
    k_agg<<<g_vec, T>>>();
    k_ovf<<<1, 256>>>(src, dst);
    k_gemm<false><<<g_gemm, T>>>(W2, b2, out);      // out = AGG*nin@W2+b2
}